// round 2
// baseline (speedup 1.0000x reference)
#include <cuda_runtime.h>
#include <math.h>

// Problem constants (shape-specialized: H=1024, N_HALF=32, L=4096, CHANNELS=1)
#define HH   1024
#define NH   32
#define LL   4096
#define TPB  128
#define CHUNK (LL / TPB)   // 32: thread t owns l = t + 128*j, j in [0,32)

// K[h,l] = 2*Re( sum_n Ceff[h,n] * dA[h,n]^l )
// x_j := Re(Ceff * dA^{l0} * (dA^128)^j) obeys x_{j+1} = p*x_j + q*x_{j-1}
// with p = 2*Re(dA^128), q = -|dA^128|^2.

__global__ void __launch_bounds__(TPB, 1)
sskernel_diag(const float* __restrict__ log_dt,
              const float* __restrict__ B_ri,
              const float* __restrict__ C_ri,
              const float* __restrict__ inv_A_real,
              const float* __restrict__ A_imag,
              float* __restrict__ out)
{
    // Per-(h,n) precomputed params, fp64 -> fp32, one slot per n.
    __shared__ float s_th[NH];    // arg(dA)
    __shared__ float s_lg[NH];    // log|dA|
    __shared__ float s_cr[NH];    // Re(Ceff)
    __shared__ float s_ci[NH];    // Im(Ceff)
    __shared__ float s_p [NH];    // 2*Re(dA^128)
    __shared__ float s_q [NH];    // -|dA^128|^2
    __shared__ float s_wr[NH];    // Re(dA^128)
    __shared__ float s_wi[NH];    // Im(dA^128)

    const int h = blockIdx.x;
    const int t = threadIdx.x;

    if (t < NH) {
        const int n  = t;
        const int hn = h * NH + n;
        double dt = exp((double)log_dt[h]);
        double Ar = -exp((double)inv_A_real[hn]);
        double Ai = (double)A_imag[hn];
        double zr = Ar * dt, zi = Ai * dt;                 // dtA
        double dr = 1.0 - 0.5 * zr, di = -0.5 * zi;        // 1 - dtA/2
        double d2 = dr * dr + di * di;
        double idr =  dr / d2, idi = -di / d2;             // 1/(1-dtA/2)
        double nr = 1.0 + 0.5 * zr, ni = 0.5 * zi;         // 1 + dtA/2
        double dAr = nr * idr - ni * idi;                  // bilinear dA
        double dAi = nr * idi + ni * idr;
        double Br = (double)B_ri[2 * hn],     Bi = (double)B_ri[2 * hn + 1];
        double Cr = (double)C_ri[2 * hn],     Ci = (double)C_ri[2 * hn + 1];
        double bcr = Br * Cr - Bi * Ci,       bci = Br * Ci + Bi * Cr;
        double cer = (bcr * idr - bci * idi) * dt;         // Ceff
        double cei = (bcr * idi + bci * idr) * dt;
        double r2  = dAr * dAr + dAi * dAi;
        double lg  = 0.5 * log(r2);
        double th  = atan2(dAi, dAr);
        // dA^128 via 7 complex squarings (fp64: exact enough, no under/overflow:
        // |dA| in ~[0.95, 1) for these shapes -> |dA^128| >= ~1e-3)
        double wr = dAr, wi = dAi;
        #pragma unroll
        for (int s = 0; s < 7; s++) {
            double tr = wr * wr - wi * wi;
            double ti = 2.0 * wr * wi;
            wr = tr; wi = ti;
        }
        s_th[n] = (float)th;
        s_lg[n] = (float)lg;
        s_cr[n] = (float)cer;
        s_ci[n] = (float)cei;
        s_p [n] = (float)(2.0 * wr);
        s_q [n] = (float)(-(wr * wr + wi * wi));
        s_wr[n] = (float)wr;
        s_wi[n] = (float)wi;
    }
    __syncthreads();

    float acc[CHUNK];
    #pragma unroll
    for (int j = 0; j < CHUNK; j++) acc[j] = 0.0f;

    const float l0 = (float)t;

    // 2-way interleave over n for ILP on the dependent FMA chains.
    #pragma unroll 2
    for (int n = 0; n < NH; n++) {
        const float th = s_th[n], lg = s_lg[n];
        const float cr = s_cr[n], ci = s_ci[n];
        const float p  = s_p [n], q  = s_q [n];
        const float wr = s_wr[n], wi = s_wi[n];

        // v = Ceff * dA^{l0};  l0 < 128 keeps l0*th small -> good fp32 accuracy
        float e = expf(l0 * lg);
        float sn, cs;
        sincosf(l0 * th, &sn, &cs);
        float vr = e * (cr * cs - ci * sn);
        float vi = e * (ci * cs + cr * sn);

        float x0 = vr;                         // x at l0
        float x1 = vr * wr - vi * wi;          // Re(v * dA^128) at l0+128
        acc[0] += x0;
        acc[1] += x1;
        #pragma unroll
        for (int j = 2; j < CHUNK; j++) {
            float x2 = fmaf(p, x1, q * x0);    // 2 FMA-class ops
            acc[j] += x2;                      // 1 add
            x0 = x1; x1 = x2;
        }
    }

    // Coalesced stores: at each j, 128 threads write 128 consecutive floats.
    float* o = out + (size_t)h * LL + t;
    #pragma unroll
    for (int j = 0; j < CHUNK; j++) o[j * TPB] = 2.0f * acc[j];
}

extern "C" void kernel_launch(void* const* d_in, const int* in_sizes, int n_in,
                              void* d_out, int out_size)
{
    const float* log_dt     = (const float*)d_in[0];   // (H,)
    const float* B_ri       = (const float*)d_in[1];   // (H, N, 2)
    const float* C_ri       = (const float*)d_in[2];   // (1, H, N, 2)
    const float* inv_A_real = (const float*)d_in[3];   // (H, N)
    const float* A_imag     = (const float*)d_in[4];   // (H, N)
    // d_in[5] = L (scalar), fixed at 4096 for this problem instance.
    float* out = (float*)d_out;                        // (1, H, L)

    sskernel_diag<<<HH, TPB>>>(log_dt, B_ri, C_ri, inv_A_real, A_imag, out);
}

// round 3
// speedup vs baseline: 1.2039x; 1.2039x over previous
#include <cuda_runtime.h>
#include <math.h>

// Shape-specialized: H=1024, N_HALF=32, L=4096, CHANNELS=1
#define HH   1024
#define NH   32
#define LL   4096
#define TPB  128
#define CHUNK (LL / TPB)   // 32: thread t owns l = t + 128*j

// K[h,l] = 2*Re( sum_n Ceff[h,n] * dA[h,n]^l )
// x_j := Re(Ceff * dA^{l0} * W^j), W = dA^128, obeys
//   x_{j+1} = p*x_j + q*x_{j-1},  p = 2*Re(W), q = -|W|^2.
// Two n-chains are packed per 64-bit f32x2 register (Blackwell packed fp32).

typedef unsigned long long u64;

__device__ __forceinline__ u64 pk2(float lo, float hi) {
    u64 r; asm("mov.b64 %0, {%1,%2};" : "=l"(r) : "f"(lo), "f"(hi)); return r;
}
__device__ __forceinline__ void upk2(float& lo, float& hi, u64 v) {
    asm("mov.b64 {%0,%1}, %2;" : "=f"(lo), "=f"(hi) : "l"(v));
}
__device__ __forceinline__ u64 mul2(u64 a, u64 b) {
    u64 r; asm("mul.rn.f32x2 %0, %1, %2;" : "=l"(r) : "l"(a), "l"(b)); return r;
}
__device__ __forceinline__ u64 fma2(u64 a, u64 b, u64 c) {
    u64 r; asm("fma.rn.f32x2 %0, %1, %2, %3;" : "=l"(r) : "l"(a), "l"(b), "l"(c)); return r;
}
__device__ __forceinline__ u64 add2(u64 a, u64 b) {
    u64 r; asm("add.rn.f32x2 %0, %1, %2;" : "=l"(r) : "l"(a), "l"(b)); return r;
}

__global__ void __launch_bounds__(TPB)
sskernel_diag(const float* __restrict__ log_dt,
              const float* __restrict__ B_ri,
              const float* __restrict__ C_ri,
              const float* __restrict__ inv_A_real,
              const float* __restrict__ A_imag,
              float* __restrict__ out)
{
    // Per-(h,n) params, computed in fp64 by the first NH threads.
    __shared__ float s_th[NH];    // arg(dA)
    __shared__ float s_lg[NH];    // log|dA|
    __shared__ float s_cr[NH];    // Re(Ceff)
    __shared__ float s_ci[NH];    // Im(Ceff)
    __shared__ float s_p [NH];    // 2*Re(W)
    __shared__ float s_q [NH];    // -|W|^2
    __shared__ float s_wr[NH];    // Re(W)
    __shared__ float s_wi[NH];    // Im(W)

    const int h = blockIdx.x;
    const int t = threadIdx.x;

    if (t < NH) {
        const int n  = t;
        const int hn = h * NH + n;
        double dt = exp((double)log_dt[h]);
        double Ar = -exp((double)inv_A_real[hn]);
        double Ai = (double)A_imag[hn];
        double zr = Ar * dt, zi = Ai * dt;                 // dtA
        double dr = 1.0 - 0.5 * zr, di = -0.5 * zi;        // 1 - dtA/2
        double d2 = dr * dr + di * di;
        double idr =  dr / d2, idi = -di / d2;             // 1/(1-dtA/2)
        double nr = 1.0 + 0.5 * zr, ni = 0.5 * zi;         // 1 + dtA/2
        double dAr = nr * idr - ni * idi;                  // bilinear dA
        double dAi = nr * idi + ni * idr;
        double Br = (double)B_ri[2 * hn],  Bi = (double)B_ri[2 * hn + 1];
        double Cr = (double)C_ri[2 * hn],  Ci = (double)C_ri[2 * hn + 1];
        double bcr = Br * Cr - Bi * Ci,    bci = Br * Ci + Bi * Cr;
        double cer = (bcr * idr - bci * idi) * dt;         // Ceff
        double cei = (bcr * idi + bci * idr) * dt;
        double r2  = dAr * dAr + dAi * dAi;
        s_lg[n] = (float)(0.5 * log(r2));
        s_th[n] = (float)atan2(dAi, dAr);
        s_cr[n] = (float)cer;
        s_ci[n] = (float)cei;
        // W = dA^128 via 7 fp64 complex squarings
        double wr = dAr, wi = dAi;
        #pragma unroll
        for (int s = 0; s < 7; s++) {
            double tr = wr * wr - wi * wi;
            double ti = 2.0 * wr * wi;
            wr = tr; wi = ti;
        }
        s_p [n] = (float)(2.0 * wr);
        s_q [n] = (float)(-(wr * wr + wi * wi));
        s_wr[n] = (float)wr;
        s_wi[n] = (float)wi;
    }
    __syncthreads();

    u64 accp[CHUNK];
    #pragma unroll
    for (int j = 0; j < CHUNK; j++) accp[j] = 0ull;

    const float l0 = (float)t;

    // Initialize one packed chain covering n-pair (n0, n0+1):
    // X0 = (x0 at l0) for both n, X1 = (x at l0+128).
    auto init_pair = [&](int n0, u64& X0, u64& X1, u64& P2, u64& Q2) {
        float x0[2], x1[2];
        #pragma unroll
        for (int k = 0; k < 2; k++) {
            const int n = n0 + k;
            const float lg = s_lg[n], th = s_th[n];
            const float cr = s_cr[n], ci = s_ci[n];
            const float wr = s_wr[n], wi = s_wi[n];
            float e = __expf(l0 * lg);           // MUFU.EX2 path
            float sn, cs;
            __sincosf(l0 * th, &sn, &cs);        // MUFU.SIN/COS path
            float vr = e * (cr * cs - ci * sn);
            float vi = e * (ci * cs + cr * sn);
            x0[k] = vr;
            x1[k] = vr * wr - vi * wi;           // Re(v * W)
        }
        X0 = pk2(x0[0], x0[1]);
        X1 = pk2(x1[0], x1[1]);
        P2 = pk2(s_p[n0], s_p[n0 + 1]);
        Q2 = pk2(s_q[n0], s_q[n0 + 1]);
    };

    // 16 n-pairs, processed two at a time (ILP=2 on the 4-cycle FFMA2 chain).
    for (int n0 = 0; n0 < NH; n0 += 4) {
        u64 XA0, XA1, PA, QA;
        u64 XB0, XB1, PB, QB;
        init_pair(n0,     XA0, XA1, PA, QA);
        init_pair(n0 + 2, XB0, XB1, PB, QB);

        accp[0] = add2(accp[0], add2(XA0, XB0));
        accp[1] = add2(accp[1], add2(XA1, XB1));

        #pragma unroll
        for (int j = 2; j < CHUNK; j++) {
            u64 XA2 = fma2(PA, XA1, mul2(QA, XA0));
            u64 XB2 = fma2(PB, XB1, mul2(QB, XB0));
            accp[j] = add2(accp[j], XA2);
            accp[j] = add2(accp[j], XB2);
            XA0 = XA1; XA1 = XA2;
            XB0 = XB1; XB1 = XB2;
        }
    }

    // Coalesced stores: at each j, 128 threads write 128 consecutive floats.
    float* o = out + (size_t)h * LL + t;
    #pragma unroll
    for (int j = 0; j < CHUNK; j++) {
        float lo, hi;
        upk2(lo, hi, accp[j]);
        o[j * TPB] = 2.0f * (lo + hi);
    }
}

extern "C" void kernel_launch(void* const* d_in, const int* in_sizes, int n_in,
                              void* d_out, int out_size)
{
    const float* log_dt     = (const float*)d_in[0];   // (H,)
    const float* B_ri       = (const float*)d_in[1];   // (H, N, 2)
    const float* C_ri       = (const float*)d_in[2];   // (1, H, N, 2)
    const float* inv_A_real = (const float*)d_in[3];   // (H, N)
    const float* A_imag     = (const float*)d_in[4];   // (H, N)
    float* out = (float*)d_out;                        // (1, H, L)

    sskernel_diag<<<HH, TPB>>>(log_dt, B_ri, C_ri, inv_A_real, A_imag, out);
}